// round 16
// baseline (speedup 1.0000x reference)
#include <cuda_runtime.h>
#include <cuda_bf16.h>
#include <math.h>
#include <stdint.h>

// Problem constants
#define Bb   32
#define Tt   2048
#define Ee   256
#define Hh   256
#define NLBL 20
#define Mrows (Bb * Tt)   // 65536
#define NPART 64          // 32-row pooling partials per batch (2048/32)

// ---------------------------------------------------------------------------
// Device scratch (round-14/15 layout).
// ---------------------------------------------------------------------------
__device__ __align__(128) unsigned char g_X2s[(size_t)1024 * 8 * 8192];   // 64 MB
__device__ __align__(128) unsigned char g_W2s[(size_t)8 * 8 * 24576];     // 1.5 MB
__device__ float g_psum[Bb * NPART * 512];
__device__ float g_pmax[Bb * NPART * 512];
__device__ float g_doc[Bb * 1024];
__device__ float g_d1[Bb * 256];

// ---------------------------------------------------------------------------
// PTX helpers
// ---------------------------------------------------------------------------
__device__ __forceinline__ uint32_t smem_u32(const void* p) {
    uint32_t a;
    asm("{ .reg .u64 t; cvta.to.shared.u64 t, %1; cvt.u32.u64 %0, t; }" : "=r"(a) : "l"(p));
    return a;
}
__device__ __forceinline__ float tanha(float x) {
    float y;
    asm("tanh.approx.f32 %0, %1;" : "=f"(y) : "f"(x));
    return y;
}

#define MBARRIER_INIT(addr, cnt) \
    asm volatile("mbarrier.init.shared.b64 [%0], %1;" :: "r"((uint32_t)(addr)), "r"((uint32_t)(cnt)) : "memory")
#define MBARRIER_INVAL(addr) \
    asm volatile("mbarrier.inval.shared.b64 [%0];" :: "r"((uint32_t)(addr)) : "memory")
#define MBARRIER_EXPECT_TX(addr, bytes) \
    asm volatile("mbarrier.arrive.expect_tx.shared.b64 _, [%0], %1;" :: "r"((uint32_t)(addr)), "r"((uint32_t)(bytes)) : "memory")

#define MBARRIER_WAIT_PARITY(mbar_smem_addr, phase_parity) do { \
    uint32_t _mbar = (uint32_t)(mbar_smem_addr); \
    uint32_t _parity = (uint32_t)(phase_parity); \
    uint32_t _done; \
    asm volatile( \
        "{\n\t.reg .pred p;\n\t" \
        "mbarrier.try_wait.parity.acquire.cta.shared::cta.b64 p, [%1], %2;\n\t" \
        "selp.b32 %0, 1, 0, p;\n\t}" \
        : "=r"(_done) : "r"(_mbar), "r"(_parity) : "memory"); \
    if (!_done) { \
        asm volatile( \
            "{\n\t.reg .pred P1;\n\t" \
            "WAIT_LOOP_%=:\n\t" \
            "mbarrier.try_wait.parity.acquire.cta.shared::cta.b64 P1, [%0], %1, 0x989680;\n\t" \
            "@P1 bra.uni WAIT_DONE_%=;\n\t" \
            "bra.uni WAIT_LOOP_%=;\n\t" \
            "WAIT_DONE_%=:\n\t}" \
            :: "r"(_mbar), "r"(_parity) : "memory"); \
    } \
} while (0)

#define CP_BULK(dst, src, sz, mbar) \
    asm volatile("cp.async.bulk.shared::cluster.global.mbarrier::complete_tx::bytes [%0], [%1], %2, [%3];" \
                 :: "r"((uint32_t)(dst)), "l"(src), "r"((uint32_t)(sz)), "r"((uint32_t)(mbar)) : "memory")

#define LDSM_X4(r0, r1, r2, r3, addr) \
    asm volatile("ldmatrix.sync.aligned.m8n8.x4.shared.b16 {%0,%1,%2,%3}, [%4];" \
                 : "=r"(r0), "=r"(r1), "=r"(r2), "=r"(r3) : "r"(addr))

#define MMA_BF16(d, a, b0, b1) \
    asm volatile("mma.sync.aligned.m16n8k16.row.col.f32.bf16.bf16.f32 " \
                 "{%0,%1,%2,%3}, {%4,%5,%6,%7}, {%8,%9}, {%0,%1,%2,%3};" \
                 : "+f"((d)[0]), "+f"((d)[1]), "+f"((d)[2]), "+f"((d)[3]) \
                 : "r"((a)[0]), "r"((a)[1]), "r"((a)[2]), "r"((a)[3]), \
                   "r"(b0), "r"(b1))

__device__ __forceinline__ uint32_t sw128(uint32_t off) {
    return off ^ ((off >> 3) & 0x70);
}

__device__ __forceinline__ uint32_t pack2(unsigned short a, unsigned short b) {
    return (uint32_t)a | ((uint32_t)b << 16);
}

// ---------------------------------------------------------------------------
// Fused converter (round 15, unchanged): blocks [0,8192) = X, [8192,8384) = W.
// ---------------------------------------------------------------------------
__global__ void conv_fused_kernel(const float* __restrict__ X,
                                  const int* __restrict__ lengths,
                                  const float* __restrict__ Wf,
                                  const float* __restrict__ Wr)
{
    if (blockIdx.x < 8192) {
        size_t i = (size_t)blockIdx.x * 256 + threadIdx.x;
        size_t row = i >> 5;
        int m = (int)(i & 31);
        int b = (int)(row >> 11);
        int t = (int)(row & 2047);
        int len;
        {
            int l = 0;
            if ((threadIdx.x & 31) == 0) l = lengths[b];
            len = __shfl_sync(0xFFFFFFFFu, l, 0);
        }
        if (len < 1) len = 1;
        if (len > Tt) len = Tt;
        if (t >= len) return;

        const float4* xp = reinterpret_cast<const float4*>(X + row * 256 + m * 8);
        float4 v0 = xp[0];
        float4 v1 = xp[1];
        float xs[8] = {v0.x, v0.y, v0.z, v0.w, v1.x, v1.y, v1.z, v1.w};
        unsigned short hi[8], lo[8];
#pragma unroll
        for (int j = 0; j < 8; j++) {
            __nv_bfloat16 h = __float2bfloat16(xs[j]);
            __nv_bfloat16 l = __float2bfloat16(xs[j] - __bfloat162float(h));
            hi[j] = __bfloat16_as_ushort(h);
            lo[j] = __bfloat16_as_ushort(l);
        }

        const int tile = (int)(row >> 6);
        const int r    = (int)(row & 63);
        const int c    = m >> 3;
        const int unit = (m & 7) ^ (r & 7);

        uint4 hv = make_uint4(pack2(hi[0], hi[1]), pack2(hi[2], hi[3]),
                              pack2(hi[4], hi[5]), pack2(hi[6], hi[7]));
        uint4 lv = make_uint4(pack2(lo[0], lo[1]), pack2(lo[2], lo[3]),
                              pack2(lo[4], lo[5]), pack2(lo[6], lo[7]));
        size_t hi_base = ((size_t)(tile * 8 + 2 * c) * 64 + r) * 128 + unit * 16;
        size_t lo_base = ((size_t)(tile * 8 + 2 * c + 1) * 64 + r) * 128 + unit * 16;
        *(uint4*)(g_X2s + hi_base) = hv;
        *(uint4*)(g_X2s + lo_base) = lv;
    } else {
        int i = (blockIdx.x - 8192) * 256 + threadIdx.x;
        int n = i >> 5;
        int m = i & 31;
        int dir = n / 768;
        int rem = n - dir * 768;
        int gate = rem >> 8;
        int jj = rem & 255;
        int gr = (gate == 0) ? jj : (gate == 1) ? 512 + jj : 768 + jj;
        const float* W = dir ? Wr : Wf;
        const float4* wp = reinterpret_cast<const float4*>(W + (size_t)gr * 256 + m * 8);
        float4 v0 = wp[0];
        float4 v1 = wp[1];
        float xs[8] = {v0.x, v0.y, v0.z, v0.w, v1.x, v1.y, v1.z, v1.w};
        unsigned short hi[8], lo[8];
#pragma unroll
        for (int j = 0; j < 8; j++) {
            __nv_bfloat16 h = __float2bfloat16(xs[j]);
            __nv_bfloat16 l = __float2bfloat16(xs[j] - __bfloat162float(h));
            hi[j] = __bfloat16_as_ushort(h);
            lo[j] = __bfloat16_as_ushort(l);
        }

        const int jq  = jj >> 6;
        const int jl  = jj & 63;
        const int r3  = (jl >> 4) * 48 + gate * 16 + (jl & 15);
        const int c   = m >> 3;
        const int unit = (m & 7) ^ (r3 & 7);
        const int img  = (dir * 4 + jq) * 8;

        uint4 hv = make_uint4(pack2(hi[0], hi[1]), pack2(hi[2], hi[3]),
                              pack2(hi[4], hi[5]), pack2(hi[6], hi[7]));
        uint4 lv = make_uint4(pack2(lo[0], lo[1]), pack2(lo[2], lo[3]),
                              pack2(lo[4], lo[5]), pack2(lo[6], lo[7]));
        size_t hi_base = ((size_t)(img + c) * 192 + r3) * 128 + unit * 16;
        size_t lo_base = ((size_t)(img + 4 + c) * 192 + r3) * 128 + unit * 16;
        *(uint4*)(g_W2s + hi_base) = hv;
        *(uint4*)(g_W2s + lo_base) = lv;
    }
}

// ---------------------------------------------------------------------------
// HMMA gates-GEMM, quarter-N tiles, occupancy 3 (round 14, unchanged).
// ---------------------------------------------------------------------------
#define SMA_SZ 8192
#define SMB_SZ 24576
#define SMO_B  16384
#define SMO_MB (SMO_B + 2 * SMB_SZ)     // 65536
#define SMEM_GEMM (SMO_MB + 64)          // 65600

__global__ __launch_bounds__(256, 3) void gemm_mma_kernel(
    const int* __restrict__ lengths,
    const float* __restrict__ bihf, const float* __restrict__ bhhf,
    const float* __restrict__ bihr, const float* __restrict__ bhhr)
{
    extern __shared__ char smem[];
    const uint32_t sb = smem_u32(smem);
    const int tid  = threadIdx.x;
    const int wid  = tid >> 5;
    const int lane = tid & 31;
    const int dir  = blockIdx.x >> 2;
    const int jq   = blockIdx.x & 3;
    const int rb   = blockIdx.y * 64;

    const int b      = rb >> 11;
    const int tstart = rb & 2047;
    int len = lengths[b];
    if (len < 1) len = 1;
    if (len > Tt) len = Tt;

    if (tstart >= len) {
        if (tid < 128) {
            const int jj = tid & 63;
            const int rh = tid >> 6;
            const int pidx = ((b << 6) + (tstart >> 5) + rh) * 512 + dir * 256 + jq * 64 + jj;
            g_psum[pidx] = 0.0f;
            g_pmax[pidx] = -1e30f;
        }
        return;
    }

    const int warpM = (wid & 1) * 32;
    const int hb    = wid >> 1;
    const int warpN = hb * 48;

    const int tile8   = (rb >> 6) * 8;
    const int imgbase = (dir * 4 + jq) * 8;

    auto bload = [](int s) { return (s >= 8) || ((s & 1) == 0); };
    auto bbuff = [](int s) { return (s < 8) ? ((s >> 1) & 1) : (s & 1); };
    auto aslab = [](int s) { return (s < 8) ? s : 2 * (s - 8); };
    auto bslab = [](int s) { return (s < 8) ? (s >> 1) : 4 + (s - 8); };

    if (tid == 0) {
        MBARRIER_INIT(sb + SMO_MB, 1);
        MBARRIER_INIT(sb + SMO_MB + 8, 1);
    }
    __syncthreads();

    auto issue = [&](int s) {
        const uint32_t mb = sb + SMO_MB + ((s & 1) << 3);
        const uint32_t bytes = SMA_SZ + (bload(s) ? SMB_SZ : 0);
        MBARRIER_EXPECT_TX(mb, bytes);
        const unsigned char* asrc = g_X2s + (size_t)(tile8 + aslab(s)) * SMA_SZ;
        CP_BULK(sb + (s & 1) * SMA_SZ, asrc, SMA_SZ, mb);
        if (bload(s)) {
            const unsigned char* bsrc = g_W2s + (size_t)(imgbase + bslab(s)) * SMB_SZ;
            CP_BULK(sb + SMO_B + bbuff(s) * SMB_SZ, bsrc, SMB_SZ, mb);
        }
    };

    if (tid == 0) issue(0);

    float acc[2][6][4];
#pragma unroll
    for (int i = 0; i < 2; i++)
#pragma unroll
        for (int j = 0; j < 6; j++)
#pragma unroll
            for (int k = 0; k < 4; k++) acc[i][j][k] = 0.0f;

    const int aL_row = ((lane >> 3) & 1) * 8 + (lane & 7);
    const int aL_k   = (lane >> 4);
    const int bL_n   = (lane >> 4) * 8 + (lane & 7);
    const int bL_k   = (lane >> 3) & 1;

    for (int s = 0; s < 12; s++) {
        if (s < 11 && tid == 0) issue(s + 1);

        MBARRIER_WAIT_PARITY(sb + SMO_MB + ((s & 1) << 3), (s >> 1) & 1);

        const uint32_t sa = sb + (s & 1) * SMA_SZ;
        const uint32_t sB = sb + SMO_B + bbuff(s) * SMB_SZ;

#pragma unroll
        for (int kk = 0; kk < 4; kk++) {
            uint32_t afr[2][4];
#pragma unroll
            for (int sub = 0; sub < 2; sub++) {
                int row = warpM + sub * 16 + aL_row;
                uint32_t off = sw128((uint32_t)(row * 128 + (kk * 2 + aL_k) * 16));
                LDSM_X4(afr[sub][0], afr[sub][1], afr[sub][2], afr[sub][3], sa + off);
            }
#pragma unroll
            for (int p = 0; p < 3; p++) {
                uint32_t b0, b1, b2, b3;
                int n = warpN + p * 16 + bL_n;
                uint32_t off = sw128((uint32_t)(n * 128 + (kk * 2 + bL_k) * 16));
                LDSM_X4(b0, b1, b2, b3, sB + off);
                MMA_BF16(acc[0][2 * p],     afr[0], b0, b1);
                MMA_BF16(acc[0][2 * p + 1], afr[0], b2, b3);
                MMA_BF16(acc[1][2 * p],     afr[1], b0, b1);
                MMA_BF16(acc[1][2 * p + 1], afr[1], b2, b3);
            }
        }
        __syncthreads();
    }

    // register-level epilogue: tanh.approx activation + masked pooling
    {
        const float* __restrict__ bih = dir ? bihr : bihf;
        const float* __restrict__ bhh = dir ? bhhr : bhhf;
        const int g  = lane >> 2;
        const int tg = lane & 3;

        const int vrw  = len - tstart - warpM;
        const int prow = (b << 6) + (tstart >> 5) + (wid & 1);
        const int pcb  = dir * 256 + jq * 64 + hb * 16;

        if (vrw <= 0) {
            if (lane < 4) {
#pragma unroll
                for (int q = 0; q < 2; q++)
#pragma unroll
                    for (int c = 0; c < 2; c++) {
                        const int pc = pcb + q * 8 + 2 * tg + c;
                        g_psum[prow * 512 + pc] = 0.0f;
                        g_pmax[prow * 512 + pc] = -1e30f;
                    }
            }
        } else {
            const bool v0 = (g)      < vrw;
            const bool v1 = (g + 8)  < vrw;
            const bool v2 = (g + 16) < vrw;
            const bool v3 = (g + 24) < vrw;
#pragma unroll
            for (int q = 0; q < 2; q++) {
#pragma unroll
                for (int c = 0; c < 2; c++) {
                    const int j = jq * 64 + hb * 16 + q * 8 + 2 * tg + c;
                    const float Bi = bih[j]       + bhh[j];
                    const float Bg = bih[512 + j] + bhh[512 + j];
                    const float Bo = bih[768 + j] + bhh[768 + j];

                    float iv[4] = {acc[0][q][c],     acc[0][q][2 + c],
                                   acc[1][q][c],     acc[1][q][2 + c]};
                    float gv[4] = {acc[0][2 + q][c], acc[0][2 + q][2 + c],
                                   acc[1][2 + q][c], acc[1][2 + q][2 + c]};
                    float ov[4] = {acc[0][4 + q][c], acc[0][4 + q][2 + c],
                                   acc[1][4 + q][c], acc[1][4 + q][2 + c]};
                    const bool vld[4] = {v0, v1, v2, v3};

                    float s = 0.0f, m = -1e30f;
#pragma unroll
                    for (int r = 0; r < 4; r++) {
                        float si = fmaf(0.5f, tanha(0.5f * (iv[r] + Bi)), 0.5f);
                        float cs = si * tanha(gv[r] + Bg);
                        float so = fmaf(0.5f, tanha(0.5f * (ov[r] + Bo)), 0.5f);
                        float h  = so * tanha(cs);
                        if (vld[r]) { s += h; m = fmaxf(m, h); }
                    }
#pragma unroll
                    for (int off = 4; off < 32; off <<= 1) {
                        s += __shfl_xor_sync(0xFFFFFFFFu, s, off);
                        m = fmaxf(m, __shfl_xor_sync(0xFFFFFFFFu, m, off));
                    }
                    if (g == 0) {
                        const int pc = pcb + q * 8 + 2 * tg + c;
                        g_psum[prow * 512 + pc] = s;
                        g_pmax[prow * 512 + pc] = m;
                    }
                }
            }
        }
    }

    __syncthreads();
    if (tid == 0) {
        MBARRIER_INVAL(sb + SMO_MB);
        MBARRIER_INVAL(sb + SMO_MB + 8);
    }
}

// ---------------------------------------------------------------------------
// Tail kernel 1: reduce 64 partials -> doc. Grid (16, 32) = 512 blocks,
// 32 cols per block (half the per-thread loads of round 13's version;
// same summation grouping -> identical results).
// ---------------------------------------------------------------------------
__global__ void reduce_kernel(const int* __restrict__ lengths)
{
    __shared__ float ss[8][32];
    __shared__ float sm[8][32];
    const int b    = blockIdx.y;
    const int cb   = blockIdx.x * 32;
    const int tid  = threadIdx.x;
    const int w    = tid >> 5;
    const int lane = tid & 31;

    int len = lengths[b];
    if (len < 1) len = 1;
    if (len > Tt) len = Tt;

    const float* ps = g_psum + (size_t)b * NPART * 512 + cb;
    const float* pm = g_pmax + (size_t)b * NPART * 512 + cb;

    float s0 = 0.f, m0 = -1e30f;
#pragma unroll
    for (int k = 0; k < 8; k++) {
        const int p = w + k * 8;
        s0 += ps[p * 512 + lane];
        m0 = fmaxf(m0, pm[p * 512 + lane]);
    }
    ss[w][lane] = s0;
    sm[w][lane] = m0;
    __syncthreads();

    if (tid < 32) {
        float S = 0.f, M = -1e30f;
#pragma unroll
        for (int w2 = 0; w2 < 8; w2++) {
            S += ss[w2][tid];
            M = fmaxf(M, sm[w2][tid]);
        }
        g_doc[b * 1024 + cb + tid]       = fmaxf(S / (float)len, 0.0f);
        g_doc[b * 1024 + 512 + cb + tid] = fmaxf(M, 0.0f);
    }
}

// ---------------------------------------------------------------------------
// Tail kernel 2: layer 1, batch-grouped. Grid (8, 4): block (og, bg) computes
// outputs og*32..+32 for batches bg*8..+8, reusing W1 registers across the 8
// batches (W1 L2 traffic 32 MB -> 4 MB). Per-lane dot order unchanged.
// ---------------------------------------------------------------------------
__global__ void mlp1_kernel(const float* __restrict__ W1, const float* __restrict__ b1)
{
    __shared__ float4 doc[8][256];
    const int og  = blockIdx.x;
    const int bg  = blockIdx.y;
    const int tid = threadIdx.x;
    const int wid = tid >> 5;
    const int lane = tid & 31;

    // Load 8 docs (8 x 1024 floats = 2048 float4), 8 per thread.
#pragma unroll
    for (int it = 0; it < 8; it++) {
        const int idx = tid + it * 256;
        const int bb  = idx >> 8;
        const int k4  = idx & 255;
        doc[bb][k4] = *(const float4*)&g_doc[(bg * 8 + bb) * 1024 + k4 * 4];
    }
    __syncthreads();

    const int n0 = og * 32 + wid * 4;
    const float4* __restrict__ w0 = (const float4*)(W1 + (size_t)(n0 + 0) * 1024);
    const float4* __restrict__ w1 = (const float4*)(W1 + (size_t)(n0 + 1) * 1024);
    const float4* __restrict__ w2 = (const float4*)(W1 + (size_t)(n0 + 2) * 1024);
    const float4* __restrict__ w3 = (const float4*)(W1 + (size_t)(n0 + 3) * 1024);

    float acc[4][8];
#pragma unroll
    for (int o = 0; o < 4; o++)
#pragma unroll
        for (int bb = 0; bb < 8; bb++) acc[o][bb] = 0.0f;

#pragma unroll
    for (int k4 = lane; k4 < 256; k4 += 32) {
        const float4 a0 = w0[k4];
        const float4 a1 = w1[k4];
        const float4 a2 = w2[k4];
        const float4 a3 = w3[k4];
#pragma unroll
        for (int bb = 0; bb < 8; bb++) {
            const float4 d = doc[bb][k4];
            acc[0][bb] = fmaf(a0.x, d.x, fmaf(a0.y, d.y, fmaf(a0.z, d.z, fmaf(a0.w, d.w, acc[0][bb]))));
            acc[1][bb] = fmaf(a1.x, d.x, fmaf(a1.y, d.y, fmaf(a1.z, d.z, fmaf(a1.w, d.w, acc[1][bb]))));
            acc[2][bb] = fmaf(a2.x, d.x, fmaf(a2.y, d.y, fmaf(a2.z, d.z, fmaf(a2.w, d.w, acc[2][bb]))));
            acc[3][bb] = fmaf(a3.x, d.x, fmaf(a3.y, d.y, fmaf(a3.z, d.z, fmaf(a3.w, d.w, acc[3][bb]))));
        }
    }

#pragma unroll
    for (int o = 0; o < 4; o++)
#pragma unroll
        for (int bb = 0; bb < 8; bb++) {
            float s = acc[o][bb];
#pragma unroll
            for (int off = 16; off > 0; off >>= 1)
                s += __shfl_xor_sync(0xFFFFFFFFu, s, off);
            if (lane == 0)
                g_d1[(bg * 8 + bb) * 256 + n0 + o] = s + b1[n0 + o];
        }
}

// ---------------------------------------------------------------------------
// Tail kernel 3: layer 2, float4. Grid 32.
// ---------------------------------------------------------------------------
__global__ void mlp2_kernel(const float* __restrict__ W2, const float* __restrict__ b2,
                            float* __restrict__ out)
{
    __shared__ float4 d1s[64];
    const int b   = blockIdx.x;
    const int tid = threadIdx.x;
    const int wid = tid >> 5;
    const int lane = tid & 31;

    if (tid < 64) d1s[tid] = *(const float4*)&g_d1[b * 256 + tid * 4];
    __syncthreads();

    for (int m = wid; m < NLBL; m += 8) {
        const float4* __restrict__ w2r = (const float4*)(W2 + m * 256);
        float s = 0.0f;
#pragma unroll
        for (int k4 = lane; k4 < 64; k4 += 32) {
            const float4 d = d1s[k4];
            const float4 a = w2r[k4];
            s = fmaf(a.x, d.x, fmaf(a.y, d.y, fmaf(a.z, d.z, fmaf(a.w, d.w, s))));
        }
#pragma unroll
        for (int off = 16; off > 0; off >>= 1)
            s += __shfl_xor_sync(0xFFFFFFFFu, s, off);
        if (lane == 0) out[b * NLBL + m] = s + b2[m];
    }
}

// ---------------------------------------------------------------------------
extern "C" void kernel_launch(void* const* d_in, const int* in_sizes, int n_in,
                              void* d_out, int out_size)
{
    const float* X    = (const float*)d_in[0];
    const int*   lens = (const int*)  d_in[1];
    const float* Wf   = (const float*)d_in[2];
    const float* bihf = (const float*)d_in[3];
    const float* bhhf = (const float*)d_in[4];
    const float* Wr   = (const float*)d_in[5];
    const float* bihr = (const float*)d_in[6];
    const float* bhhr = (const float*)d_in[7];
    const float* W1   = (const float*)d_in[8];
    const float* b1   = (const float*)d_in[9];
    const float* W2   = (const float*)d_in[10];
    const float* b2   = (const float*)d_in[11];
    float* out = (float*)d_out;

    cudaFuncSetAttribute(gemm_mma_kernel, cudaFuncAttributeMaxDynamicSharedMemorySize, SMEM_GEMM);

    conv_fused_kernel<<<8384, 256>>>(X, lens, Wf, Wr);

    dim3 gG(8, 1024);
    gemm_mma_kernel<<<gG, 256, SMEM_GEMM>>>(lens, bihf, bhhf, bihr, bhhr);

    dim3 gR(16, Bb);
    reduce_kernel<<<gR, 256>>>(lens);
    dim3 gM1(8, 4);
    mlp1_kernel<<<gM1, 256>>>(W1, b1);
    mlp2_kernel<<<Bb, 256>>>(W2, b2, out);
}

// round 17
// speedup vs baseline: 1.0190x; 1.0190x over previous
#include <cuda_runtime.h>
#include <cuda_bf16.h>
#include <math.h>
#include <stdint.h>

// Problem constants
#define Bb   32
#define Tt   2048
#define Ee   256
#define Hh   256
#define NLBL 20
#define Mrows (Bb * Tt)   // 65536
#define NPART 64          // 32-row pooling partials per batch (2048/32)

// ---------------------------------------------------------------------------
// Device scratch (round-14/15 layout).
// ---------------------------------------------------------------------------
__device__ __align__(128) unsigned char g_X2s[(size_t)1024 * 8 * 8192];   // 64 MB
__device__ __align__(128) unsigned char g_W2s[(size_t)8 * 8 * 24576];     // 1.5 MB
__device__ float g_psum[Bb * NPART * 512];
__device__ float g_pmax[Bb * NPART * 512];
__device__ float g_doc[Bb * 1024];
__device__ float g_d1[Bb * 256];

// ---------------------------------------------------------------------------
// PTX helpers
// ---------------------------------------------------------------------------
__device__ __forceinline__ uint32_t smem_u32(const void* p) {
    uint32_t a;
    asm("{ .reg .u64 t; cvta.to.shared.u64 t, %1; cvt.u32.u64 %0, t; }" : "=r"(a) : "l"(p));
    return a;
}
__device__ __forceinline__ float tanha(float x) {
    float y;
    asm("tanh.approx.f32 %0, %1;" : "=f"(y) : "f"(x));
    return y;
}

#define MBARRIER_INIT(addr, cnt) \
    asm volatile("mbarrier.init.shared.b64 [%0], %1;" :: "r"((uint32_t)(addr)), "r"((uint32_t)(cnt)) : "memory")
#define MBARRIER_INVAL(addr) \
    asm volatile("mbarrier.inval.shared.b64 [%0];" :: "r"((uint32_t)(addr)) : "memory")
#define MBARRIER_EXPECT_TX(addr, bytes) \
    asm volatile("mbarrier.arrive.expect_tx.shared.b64 _, [%0], %1;" :: "r"((uint32_t)(addr)), "r"((uint32_t)(bytes)) : "memory")

#define MBARRIER_WAIT_PARITY(mbar_smem_addr, phase_parity) do { \
    uint32_t _mbar = (uint32_t)(mbar_smem_addr); \
    uint32_t _parity = (uint32_t)(phase_parity); \
    uint32_t _done; \
    asm volatile( \
        "{\n\t.reg .pred p;\n\t" \
        "mbarrier.try_wait.parity.acquire.cta.shared::cta.b64 p, [%1], %2;\n\t" \
        "selp.b32 %0, 1, 0, p;\n\t}" \
        : "=r"(_done) : "r"(_mbar), "r"(_parity) : "memory"); \
    if (!_done) { \
        asm volatile( \
            "{\n\t.reg .pred P1;\n\t" \
            "WAIT_LOOP_%=:\n\t" \
            "mbarrier.try_wait.parity.acquire.cta.shared::cta.b64 P1, [%0], %1, 0x989680;\n\t" \
            "@P1 bra.uni WAIT_DONE_%=;\n\t" \
            "bra.uni WAIT_LOOP_%=;\n\t" \
            "WAIT_DONE_%=:\n\t}" \
            :: "r"(_mbar), "r"(_parity) : "memory"); \
    } \
} while (0)

#define CP_BULK(dst, src, sz, mbar) \
    asm volatile("cp.async.bulk.shared::cluster.global.mbarrier::complete_tx::bytes [%0], [%1], %2, [%3];" \
                 :: "r"((uint32_t)(dst)), "l"(src), "r"((uint32_t)(sz)), "r"((uint32_t)(mbar)) : "memory")

#define LDSM_X4(r0, r1, r2, r3, addr) \
    asm volatile("ldmatrix.sync.aligned.m8n8.x4.shared.b16 {%0,%1,%2,%3}, [%4];" \
                 : "=r"(r0), "=r"(r1), "=r"(r2), "=r"(r3) : "r"(addr))

#define MMA_BF16(d, a, b0, b1) \
    asm volatile("mma.sync.aligned.m16n8k16.row.col.f32.bf16.bf16.f32 " \
                 "{%0,%1,%2,%3}, {%4,%5,%6,%7}, {%8,%9}, {%0,%1,%2,%3};" \
                 : "+f"((d)[0]), "+f"((d)[1]), "+f"((d)[2]), "+f"((d)[3]) \
                 : "r"((a)[0]), "r"((a)[1]), "r"((a)[2]), "r"((a)[3]), \
                   "r"(b0), "r"(b1))

__device__ __forceinline__ uint32_t sw128(uint32_t off) {
    return off ^ ((off >> 3) & 0x70);
}

__device__ __forceinline__ uint32_t pack2(unsigned short a, unsigned short b) {
    return (uint32_t)a | ((uint32_t)b << 16);
}

// ---------------------------------------------------------------------------
// Fused converter (round 15, unchanged): blocks [0,8192) = X, [8192,8384) = W.
// ---------------------------------------------------------------------------
__global__ void conv_fused_kernel(const float* __restrict__ X,
                                  const int* __restrict__ lengths,
                                  const float* __restrict__ Wf,
                                  const float* __restrict__ Wr)
{
    if (blockIdx.x < 8192) {
        size_t i = (size_t)blockIdx.x * 256 + threadIdx.x;
        size_t row = i >> 5;
        int m = (int)(i & 31);
        int b = (int)(row >> 11);
        int t = (int)(row & 2047);
        int len;
        {
            int l = 0;
            if ((threadIdx.x & 31) == 0) l = lengths[b];
            len = __shfl_sync(0xFFFFFFFFu, l, 0);
        }
        if (len < 1) len = 1;
        if (len > Tt) len = Tt;
        if (t >= len) return;

        const float4* xp = reinterpret_cast<const float4*>(X + row * 256 + m * 8);
        float4 v0 = xp[0];
        float4 v1 = xp[1];
        float xs[8] = {v0.x, v0.y, v0.z, v0.w, v1.x, v1.y, v1.z, v1.w};
        unsigned short hi[8], lo[8];
#pragma unroll
        for (int j = 0; j < 8; j++) {
            __nv_bfloat16 h = __float2bfloat16(xs[j]);
            __nv_bfloat16 l = __float2bfloat16(xs[j] - __bfloat162float(h));
            hi[j] = __bfloat16_as_ushort(h);
            lo[j] = __bfloat16_as_ushort(l);
        }

        const int tile = (int)(row >> 6);
        const int r    = (int)(row & 63);
        const int c    = m >> 3;
        const int unit = (m & 7) ^ (r & 7);

        uint4 hv = make_uint4(pack2(hi[0], hi[1]), pack2(hi[2], hi[3]),
                              pack2(hi[4], hi[5]), pack2(hi[6], hi[7]));
        uint4 lv = make_uint4(pack2(lo[0], lo[1]), pack2(lo[2], lo[3]),
                              pack2(lo[4], lo[5]), pack2(lo[6], lo[7]));
        size_t hi_base = ((size_t)(tile * 8 + 2 * c) * 64 + r) * 128 + unit * 16;
        size_t lo_base = ((size_t)(tile * 8 + 2 * c + 1) * 64 + r) * 128 + unit * 16;
        *(uint4*)(g_X2s + hi_base) = hv;
        *(uint4*)(g_X2s + lo_base) = lv;
    } else {
        int i = (blockIdx.x - 8192) * 256 + threadIdx.x;
        int n = i >> 5;
        int m = i & 31;
        int dir = n / 768;
        int rem = n - dir * 768;
        int gate = rem >> 8;
        int jj = rem & 255;
        int gr = (gate == 0) ? jj : (gate == 1) ? 512 + jj : 768 + jj;
        const float* W = dir ? Wr : Wf;
        const float4* wp = reinterpret_cast<const float4*>(W + (size_t)gr * 256 + m * 8);
        float4 v0 = wp[0];
        float4 v1 = wp[1];
        float xs[8] = {v0.x, v0.y, v0.z, v0.w, v1.x, v1.y, v1.z, v1.w};
        unsigned short hi[8], lo[8];
#pragma unroll
        for (int j = 0; j < 8; j++) {
            __nv_bfloat16 h = __float2bfloat16(xs[j]);
            __nv_bfloat16 l = __float2bfloat16(xs[j] - __bfloat162float(h));
            hi[j] = __bfloat16_as_ushort(h);
            lo[j] = __bfloat16_as_ushort(l);
        }

        const int jq  = jj >> 6;
        const int jl  = jj & 63;
        const int r3  = (jl >> 4) * 48 + gate * 16 + (jl & 15);
        const int c   = m >> 3;
        const int unit = (m & 7) ^ (r3 & 7);
        const int img  = (dir * 4 + jq) * 8;

        uint4 hv = make_uint4(pack2(hi[0], hi[1]), pack2(hi[2], hi[3]),
                              pack2(hi[4], hi[5]), pack2(hi[6], hi[7]));
        uint4 lv = make_uint4(pack2(lo[0], lo[1]), pack2(lo[2], lo[3]),
                              pack2(lo[4], lo[5]), pack2(lo[6], lo[7]));
        size_t hi_base = ((size_t)(img + c) * 192 + r3) * 128 + unit * 16;
        size_t lo_base = ((size_t)(img + 4 + c) * 192 + r3) * 128 + unit * 16;
        *(uint4*)(g_W2s + hi_base) = hv;
        *(uint4*)(g_W2s + lo_base) = lv;
    }
}

// ---------------------------------------------------------------------------
// HMMA gates-GEMM, quarter-N tiles, occupancy 3 (round 14, unchanged).
// ---------------------------------------------------------------------------
#define SMA_SZ 8192
#define SMB_SZ 24576
#define SMO_B  16384
#define SMO_MB (SMO_B + 2 * SMB_SZ)     // 65536
#define SMEM_GEMM (SMO_MB + 64)          // 65600

__global__ __launch_bounds__(256, 3) void gemm_mma_kernel(
    const int* __restrict__ lengths,
    const float* __restrict__ bihf, const float* __restrict__ bhhf,
    const float* __restrict__ bihr, const float* __restrict__ bhhr)
{
    extern __shared__ char smem[];
    const uint32_t sb = smem_u32(smem);
    const int tid  = threadIdx.x;
    const int wid  = tid >> 5;
    const int lane = tid & 31;
    const int dir  = blockIdx.x >> 2;
    const int jq   = blockIdx.x & 3;
    const int rb   = blockIdx.y * 64;

    const int b      = rb >> 11;
    const int tstart = rb & 2047;
    int len = lengths[b];
    if (len < 1) len = 1;
    if (len > Tt) len = Tt;

    if (tstart >= len) {
        if (tid < 128) {
            const int jj = tid & 63;
            const int rh = tid >> 6;
            const int pidx = ((b << 6) + (tstart >> 5) + rh) * 512 + dir * 256 + jq * 64 + jj;
            g_psum[pidx] = 0.0f;
            g_pmax[pidx] = -1e30f;
        }
        return;
    }

    const int warpM = (wid & 1) * 32;
    const int hb    = wid >> 1;
    const int warpN = hb * 48;

    const int tile8   = (rb >> 6) * 8;
    const int imgbase = (dir * 4 + jq) * 8;

    auto bload = [](int s) { return (s >= 8) || ((s & 1) == 0); };
    auto bbuff = [](int s) { return (s < 8) ? ((s >> 1) & 1) : (s & 1); };
    auto aslab = [](int s) { return (s < 8) ? s : 2 * (s - 8); };
    auto bslab = [](int s) { return (s < 8) ? (s >> 1) : 4 + (s - 8); };

    if (tid == 0) {
        MBARRIER_INIT(sb + SMO_MB, 1);
        MBARRIER_INIT(sb + SMO_MB + 8, 1);
    }
    __syncthreads();

    auto issue = [&](int s) {
        const uint32_t mb = sb + SMO_MB + ((s & 1) << 3);
        const uint32_t bytes = SMA_SZ + (bload(s) ? SMB_SZ : 0);
        MBARRIER_EXPECT_TX(mb, bytes);
        const unsigned char* asrc = g_X2s + (size_t)(tile8 + aslab(s)) * SMA_SZ;
        CP_BULK(sb + (s & 1) * SMA_SZ, asrc, SMA_SZ, mb);
        if (bload(s)) {
            const unsigned char* bsrc = g_W2s + (size_t)(imgbase + bslab(s)) * SMB_SZ;
            CP_BULK(sb + SMO_B + bbuff(s) * SMB_SZ, bsrc, SMB_SZ, mb);
        }
    };

    if (tid == 0) issue(0);

    float acc[2][6][4];
#pragma unroll
    for (int i = 0; i < 2; i++)
#pragma unroll
        for (int j = 0; j < 6; j++)
#pragma unroll
            for (int k = 0; k < 4; k++) acc[i][j][k] = 0.0f;

    const int aL_row = ((lane >> 3) & 1) * 8 + (lane & 7);
    const int aL_k   = (lane >> 4);
    const int bL_n   = (lane >> 4) * 8 + (lane & 7);
    const int bL_k   = (lane >> 3) & 1;

    for (int s = 0; s < 12; s++) {
        if (s < 11 && tid == 0) issue(s + 1);

        MBARRIER_WAIT_PARITY(sb + SMO_MB + ((s & 1) << 3), (s >> 1) & 1);

        const uint32_t sa = sb + (s & 1) * SMA_SZ;
        const uint32_t sB = sb + SMO_B + bbuff(s) * SMB_SZ;

#pragma unroll
        for (int kk = 0; kk < 4; kk++) {
            uint32_t afr[2][4];
#pragma unroll
            for (int sub = 0; sub < 2; sub++) {
                int row = warpM + sub * 16 + aL_row;
                uint32_t off = sw128((uint32_t)(row * 128 + (kk * 2 + aL_k) * 16));
                LDSM_X4(afr[sub][0], afr[sub][1], afr[sub][2], afr[sub][3], sa + off);
            }
#pragma unroll
            for (int p = 0; p < 3; p++) {
                uint32_t b0, b1, b2, b3;
                int n = warpN + p * 16 + bL_n;
                uint32_t off = sw128((uint32_t)(n * 128 + (kk * 2 + bL_k) * 16));
                LDSM_X4(b0, b1, b2, b3, sB + off);
                MMA_BF16(acc[0][2 * p],     afr[0], b0, b1);
                MMA_BF16(acc[0][2 * p + 1], afr[0], b2, b3);
                MMA_BF16(acc[1][2 * p],     afr[1], b0, b1);
                MMA_BF16(acc[1][2 * p + 1], afr[1], b2, b3);
            }
        }
        __syncthreads();
    }

    // register-level epilogue: tanh.approx activation + masked pooling
    {
        const float* __restrict__ bih = dir ? bihr : bihf;
        const float* __restrict__ bhh = dir ? bhhr : bhhf;
        const int g  = lane >> 2;
        const int tg = lane & 3;

        const int vrw  = len - tstart - warpM;
        const int prow = (b << 6) + (tstart >> 5) + (wid & 1);
        const int pcb  = dir * 256 + jq * 64 + hb * 16;

        if (vrw <= 0) {
            if (lane < 4) {
#pragma unroll
                for (int q = 0; q < 2; q++)
#pragma unroll
                    for (int c = 0; c < 2; c++) {
                        const int pc = pcb + q * 8 + 2 * tg + c;
                        g_psum[prow * 512 + pc] = 0.0f;
                        g_pmax[prow * 512 + pc] = -1e30f;
                    }
            }
        } else {
            const bool v0 = (g)      < vrw;
            const bool v1 = (g + 8)  < vrw;
            const bool v2 = (g + 16) < vrw;
            const bool v3 = (g + 24) < vrw;
#pragma unroll
            for (int q = 0; q < 2; q++) {
#pragma unroll
                for (int c = 0; c < 2; c++) {
                    const int j = jq * 64 + hb * 16 + q * 8 + 2 * tg + c;
                    const float Bi = bih[j]       + bhh[j];
                    const float Bg = bih[512 + j] + bhh[512 + j];
                    const float Bo = bih[768 + j] + bhh[768 + j];

                    float iv[4] = {acc[0][q][c],     acc[0][q][2 + c],
                                   acc[1][q][c],     acc[1][q][2 + c]};
                    float gv[4] = {acc[0][2 + q][c], acc[0][2 + q][2 + c],
                                   acc[1][2 + q][c], acc[1][2 + q][2 + c]};
                    float ov[4] = {acc[0][4 + q][c], acc[0][4 + q][2 + c],
                                   acc[1][4 + q][c], acc[1][4 + q][2 + c]};
                    const bool vld[4] = {v0, v1, v2, v3};

                    float s = 0.0f, m = -1e30f;
#pragma unroll
                    for (int r = 0; r < 4; r++) {
                        float si = fmaf(0.5f, tanha(0.5f * (iv[r] + Bi)), 0.5f);
                        float cs = si * tanha(gv[r] + Bg);
                        float so = fmaf(0.5f, tanha(0.5f * (ov[r] + Bo)), 0.5f);
                        float h  = so * tanha(cs);
                        if (vld[r]) { s += h; m = fmaxf(m, h); }
                    }
#pragma unroll
                    for (int off = 4; off < 32; off <<= 1) {
                        s += __shfl_xor_sync(0xFFFFFFFFu, s, off);
                        m = fmaxf(m, __shfl_xor_sync(0xFFFFFFFFu, m, off));
                    }
                    if (g == 0) {
                        const int pc = pcb + q * 8 + 2 * tg + c;
                        g_psum[prow * 512 + pc] = s;
                        g_pmax[prow * 512 + pc] = m;
                    }
                }
            }
        }
    }

    __syncthreads();
    if (tid == 0) {
        MBARRIER_INVAL(sb + SMO_MB);
        MBARRIER_INVAL(sb + SMO_MB + 8);
    }
}

// ---------------------------------------------------------------------------
// Tail kernel 1: reduce 64 partials -> doc. Grid (16, 32) (round 16 version).
// ---------------------------------------------------------------------------
__global__ void reduce_kernel(const int* __restrict__ lengths)
{
    __shared__ float ss[8][32];
    __shared__ float sm[8][32];
    const int b    = blockIdx.y;
    const int cb   = blockIdx.x * 32;
    const int tid  = threadIdx.x;
    const int w    = tid >> 5;
    const int lane = tid & 31;

    int len = lengths[b];
    if (len < 1) len = 1;
    if (len > Tt) len = Tt;

    const float* ps = g_psum + (size_t)b * NPART * 512 + cb;
    const float* pm = g_pmax + (size_t)b * NPART * 512 + cb;

    float s0 = 0.f, m0 = -1e30f;
#pragma unroll
    for (int k = 0; k < 8; k++) {
        const int p = w + k * 8;
        s0 += ps[p * 512 + lane];
        m0 = fmaxf(m0, pm[p * 512 + lane]);
    }
    ss[w][lane] = s0;
    sm[w][lane] = m0;
    __syncthreads();

    if (tid < 32) {
        float S = 0.f, M = -1e30f;
#pragma unroll
        for (int w2 = 0; w2 < 8; w2++) {
            S += ss[w2][tid];
            M = fmaxf(M, sm[w2][tid]);
        }
        g_doc[b * 1024 + cb + tid]       = fmaxf(S / (float)len, 0.0f);
        g_doc[b * 1024 + 512 + cb + tid] = fmaxf(M, 0.0f);
    }
}

// ---------------------------------------------------------------------------
// Tail kernel 2: layer 1, max-TLP. Grid (16, 32) = 512 blocks: block (og, b)
// computes d1 outputs og*16..+16 for batch b; 2 outputs per warp, 8 float4
// iterations per chain. Per-output dot order unchanged -> identical results.
// ---------------------------------------------------------------------------
__global__ void mlp1_kernel(const float* __restrict__ W1, const float* __restrict__ b1)
{
    __shared__ float4 doc[256];
    const int og  = blockIdx.x;
    const int b   = blockIdx.y;
    const int tid = threadIdx.x;
    const int wid = tid >> 5;
    const int lane = tid & 31;

    doc[tid] = *(const float4*)&g_doc[b * 1024 + tid * 4];
    __syncthreads();

    const int n0 = og * 16 + wid * 2;
    const float4* __restrict__ w0 = (const float4*)(W1 + (size_t)(n0 + 0) * 1024);
    const float4* __restrict__ w1 = (const float4*)(W1 + (size_t)(n0 + 1) * 1024);

    float s0 = 0.f, s1 = 0.f;
#pragma unroll
    for (int k4 = lane; k4 < 256; k4 += 32) {
        const float4 d = doc[k4];
        float4 a = w0[k4];
        s0 = fmaf(a.x, d.x, fmaf(a.y, d.y, fmaf(a.z, d.z, fmaf(a.w, d.w, s0))));
        a = w1[k4];
        s1 = fmaf(a.x, d.x, fmaf(a.y, d.y, fmaf(a.z, d.z, fmaf(a.w, d.w, s1))));
    }
#pragma unroll
    for (int off = 16; off > 0; off >>= 1) {
        s0 += __shfl_xor_sync(0xFFFFFFFFu, s0, off);
        s1 += __shfl_xor_sync(0xFFFFFFFFu, s1, off);
    }
    if (lane == 0) {
        g_d1[b * 256 + n0 + 0] = s0 + b1[n0 + 0];
        g_d1[b * 256 + n0 + 1] = s1 + b1[n0 + 1];
    }
}

// ---------------------------------------------------------------------------
// Tail kernel 3: layer 2, float4. Grid 32.
// ---------------------------------------------------------------------------
__global__ void mlp2_kernel(const float* __restrict__ W2, const float* __restrict__ b2,
                            float* __restrict__ out)
{
    __shared__ float4 d1s[64];
    const int b   = blockIdx.x;
    const int tid = threadIdx.x;
    const int wid = tid >> 5;
    const int lane = tid & 31;

    if (tid < 64) d1s[tid] = *(const float4*)&g_d1[b * 256 + tid * 4];
    __syncthreads();

    for (int m = wid; m < NLBL; m += 8) {
        const float4* __restrict__ w2r = (const float4*)(W2 + m * 256);
        float s = 0.0f;
#pragma unroll
        for (int k4 = lane; k4 < 64; k4 += 32) {
            const float4 d = d1s[k4];
            const float4 a = w2r[k4];
            s = fmaf(a.x, d.x, fmaf(a.y, d.y, fmaf(a.z, d.z, fmaf(a.w, d.w, s))));
        }
#pragma unroll
        for (int off = 16; off > 0; off >>= 1)
            s += __shfl_xor_sync(0xFFFFFFFFu, s, off);
        if (lane == 0) out[b * NLBL + m] = s + b2[m];
    }
}

// ---------------------------------------------------------------------------
extern "C" void kernel_launch(void* const* d_in, const int* in_sizes, int n_in,
                              void* d_out, int out_size)
{
    const float* X    = (const float*)d_in[0];
    const int*   lens = (const int*)  d_in[1];
    const float* Wf   = (const float*)d_in[2];
    const float* bihf = (const float*)d_in[3];
    const float* bhhf = (const float*)d_in[4];
    const float* Wr   = (const float*)d_in[5];
    const float* bihr = (const float*)d_in[6];
    const float* bhhr = (const float*)d_in[7];
    const float* W1   = (const float*)d_in[8];
    const float* b1   = (const float*)d_in[9];
    const float* W2   = (const float*)d_in[10];
    const float* b2   = (const float*)d_in[11];
    float* out = (float*)d_out;

    cudaFuncSetAttribute(gemm_mma_kernel, cudaFuncAttributeMaxDynamicSharedMemorySize, SMEM_GEMM);

    conv_fused_kernel<<<8384, 256>>>(X, lens, Wf, Wr);

    dim3 gG(8, 1024);
    gemm_mma_kernel<<<gG, 256, SMEM_GEMM>>>(lens, bihf, bhhf, bihr, bhhr);

    dim3 gR(16, Bb);
    reduce_kernel<<<gR, 256>>>(lens);
    dim3 gM1(16, Bb);
    mlp1_kernel<<<gM1, 256>>>(W1, b1);
    mlp2_kernel<<<Bb, 256>>>(W2, b2, out);
}